// round 7
// baseline (speedup 1.0000x reference)
#include <cuda_runtime.h>

#define NHEADS  20
#define NUM_EX  13
#define TPB     128

// E' table (per-sample indexed): [h][idx][12] = 3120 floats (smem)
#define E_SIZE   3120
// Uniform weight blob -> __constant__: per head 64 floats:
//   [0..11] W1f c=0  [12..23] W1f c=1  [24..35] W1f c=2
//   [36..47] w2a=0.505*W2  [48..59] w2b=0.495*W2  [60] b2  [61] Wo
// plus [1280] = bo
#define W_SIZE   1281
#define PREP_N   (E_SIZE + W_SIZE)

__device__ float g_e[E_SIZE];
__device__ float g_w[W_SIZE + 3];
__constant__ float c_w[W_SIZE + 3];

// ---------------------------------------------------------------------------
// Prep: fold Wf/bf/emb/b1 into E'; fold leaky slopes into W2.
// ---------------------------------------------------------------------------
__global__ void prep_kernel(const float* __restrict__ emb, const float* __restrict__ Wf,
                            const float* __restrict__ bf,  const float* __restrict__ W1,
                            const float* __restrict__ b1,  const float* __restrict__ W2,
                            const float* __restrict__ b2,  const float* __restrict__ Wo,
                            const float* __restrict__ bo) {
    int t = blockIdx.x * blockDim.x + threadIdx.x;
    if (t >= PREP_N) return;
    if (t < E_SIZE) {
        int j = t % 12; int r = t / 12; int idx = r % NUM_EX; int h = r / NUM_EX;
        float v = 0.0f;
        if (j < 10) {
            v = b1[h * 10 + j];
            #pragma unroll
            for (int c = 0; c < 3; c++) v += emb[idx * 3 + c] * W1[(h * 8 + c) * 10 + j];
            #pragma unroll
            for (int i = 0; i < 5; i++) v += bf[i] * W1[(h * 8 + 3 + i) * 10 + j];
        }
        g_e[t] = v;
        return;
    }
    int u = t - E_SIZE;
    float v = 0.0f;
    if (u < 1280) {
        int h = u / 64; int o = u % 64;
        if (o < 36) {
            int c = o / 12; int j = o % 12;
            if (j < 10) {
                #pragma unroll
                for (int i = 0; i < 5; i++) v += Wf[c * 5 + i] * W1[(h * 8 + 3 + i) * 10 + j];
            }
        } else if (o < 48) {
            int j = o - 36; if (j < 10) v = 0.505f * W2[h * 10 + j];
        } else if (o < 60) {
            int j = o - 48; if (j < 10) v = 0.495f * W2[h * 10 + j];
        } else if (o == 60) {
            v = b2[h];
        } else if (o == 61) {
            v = Wo[h];
        }
    } else {
        v = bo[0];
    }
    g_w[u] = v;
}

__device__ __forceinline__ float fabs_bits(float x) {
    return __int_as_float(__float_as_int(x) & 0x7FFFFFFF);
}

// ---------------------------------------------------------------------------
// Main: f staged through smem with coalesced LDG (kills the 240B-stride
// wavefront blowup); E' in smem; uniform weights from __constant__.
// ---------------------------------------------------------------------------
__global__ __launch_bounds__(TPB) void airfit_kernel(const int* __restrict__ e,
                                                     const float* __restrict__ f,
                                                     float* __restrict__ out, int B) {
    __shared__ __align__(16) float4 sF[TPB * 15];   // 30720 B, row = 15 float4/sample
    __shared__ __align__(16) float  sE[E_SIZE];     // 12480 B

    // stage f tile, fully coalesced: 15 LDG.128 of consecutive lanes
    {
        const float4* fg = reinterpret_cast<const float4*>(f);
        size_t base = (size_t)blockIdx.x * TPB * 15;
        size_t lim  = (size_t)B * 15;
        #pragma unroll
        for (int k = 0; k < 15; k++) {
            size_t idx = base + k * TPB + threadIdx.x;
            if (idx < lim) sF[k * TPB + threadIdx.x] = fg[idx];
        }
    }
    for (int i = threadIdx.x; i < E_SIZE; i += TPB) sE[i] = g_e[i];
    __syncthreads();

    int s = blockIdx.x * TPB + threadIdx.x;
    if (s >= B) return;

    const int4*   e4  = reinterpret_cast<const int4*>(e) + (size_t)s * 5;
    const float4* myF = sF + threadIdx.x * 15;      // stride 15 f4 -> conflict-free

    float res = c_w[1280];

    #pragma unroll
    for (int hg = 0; hg < 5; hg++) {
        float4 fA = myF[hg * 3 + 0];
        float4 fB = myF[hg * 3 + 1];
        float4 fC = myF[hg * 3 + 2];
        int4   ev = __ldg(&e4[hg]);
        float g[12] = {fA.x, fA.y, fA.z, fA.w, fB.x, fB.y, fB.z, fB.w,
                       fC.x, fC.y, fC.z, fC.w};
        int idx[4] = {ev.x, ev.y, ev.z, ev.w};

        #pragma unroll
        for (int k = 0; k < 4; k++) {
            const int h = hg * 4 + k;
            const int wb = h * 64;

            const float* Er = &sE[(h * NUM_EX + idx[k]) * 12];
            float4 A0 = *reinterpret_cast<const float4*>(Er);
            float4 A1 = *reinterpret_cast<const float4*>(Er + 4);
            float2 A2 = *reinterpret_cast<const float2*>(Er + 8);
            float a[10] = {A0.x, A0.y, A0.z, A0.w, A1.x, A1.y, A1.z, A1.w, A2.x, A2.y};

            #pragma unroll
            for (int c = 0; c < 3; c++) {
                float fv = g[k * 3 + c];
                #pragma unroll
                for (int j = 0; j < 10; j++)
                    a[j] = fmaf(fv, c_w[wb + c * 12 + j], a[j]);
            }

            // leaky folded: d = b2 + sum a_j*(0.505 w2_j) + |a_j|*(0.495 w2_j)
            float d = c_w[wb + 60];
            #pragma unroll
            for (int j = 0; j < 10; j++) {
                d = fmaf(a[j],            c_w[wb + 36 + j], d);
                d = fmaf(fabs_bits(a[j]), c_w[wb + 48 + j], d);
            }

            // softplus(d) = max(d,0) + log(1+exp(-|d|))
            float m = fmaxf(d, 0.0f);
            float z = __expf(-fabsf(d));
            float spv = m + __logf(1.0f + z);

            res = fmaf(spv, c_w[wb + 61], res);
        }
    }
    out[s] = res;
}

// ---------------------------------------------------------------------------
extern "C" void kernel_launch(void* const* d_in, const int* in_sizes, int n_in,
                              void* d_out, int out_size) {
    const int*   e   = (const int*)  d_in[0];
    const float* f   = (const float*)d_in[1];
    const float* emb = (const float*)d_in[2];
    const float* Wf  = (const float*)d_in[3];
    const float* bf  = (const float*)d_in[4];
    const float* W1  = (const float*)d_in[5];
    const float* b1  = (const float*)d_in[6];
    const float* W2  = (const float*)d_in[7];
    const float* b2  = (const float*)d_in[8];
    const float* Wo  = (const float*)d_in[9];
    const float* bo  = (const float*)d_in[10];
    float* out = (float*)d_out;
    int B = out_size;

    prep_kernel<<<(PREP_N + 255) / 256, 256>>>(emb, Wf, bf, W1, b1, W2, b2, Wo, bo);

    void* c_addr = nullptr;
    void* g_addr = nullptr;
    cudaGetSymbolAddress(&c_addr, c_w);
    cudaGetSymbolAddress(&g_addr, g_w);
    cudaMemcpyAsync(c_addr, g_addr, W_SIZE * sizeof(float), cudaMemcpyDeviceToDevice);

    airfit_kernel<<<(B + TPB - 1) / TPB, TPB>>>(e, f, out, B);
}

// round 8
// speedup vs baseline: 1.2497x; 1.2497x over previous
#include <cuda_runtime.h>
#include <cstdint>

#define NHEADS  20
#define NUM_EX  13
#define TPB     128

#define E_SIZE   3120            // E' floats: [h][idx][12]
#define W_SIZE   1281

// dynamic smem layout (bytes)
#define SM_F      0              // f tile   : 128*240 = 30720
#define SM_EV     30720          // e tile   : 128*80  = 10240
#define SM_E      40960          // E' table : 12480
#define SM_MBAR   53440          // mbarrier : 8
#define SM_TOTAL  53504

#define F_TILE_B  30720
#define E_TILE_B  10240
#define EP_B      12480

__device__ __align__(16) float g_e[E_SIZE];
__device__ float g_w[W_SIZE + 3];
__constant__ float c_w[W_SIZE + 3];

// ---------------- PTX helpers ----------------
__device__ __forceinline__ uint32_t smem_u32(const void* p) {
    uint32_t a;
    asm("{ .reg .u64 t; cvta.to.shared.u64 t, %1; cvt.u32.u64 %0, t; }" : "=r"(a) : "l"(p));
    return a;
}
__device__ __forceinline__ void mbar_init(uint32_t m, uint32_t cnt) {
    asm volatile("mbarrier.init.shared.b64 [%0], %1;" :: "r"(m), "r"(cnt) : "memory");
}
__device__ __forceinline__ void mbar_expect_tx(uint32_t m, uint32_t bytes) {
    asm volatile("mbarrier.arrive.expect_tx.shared.b64 _, [%0], %1;" :: "r"(m), "r"(bytes) : "memory");
}
__device__ __forceinline__ void bulk_g2s(uint32_t dst, const void* src, uint32_t bytes, uint32_t m) {
    asm volatile("cp.async.bulk.shared::cta.global.mbarrier::complete_tx::bytes [%0], [%1], %2, [%3];"
                 :: "r"(dst), "l"(src), "r"(bytes), "r"(m) : "memory");
}
__device__ __forceinline__ void mbar_wait(uint32_t m, uint32_t parity) {
    uint32_t done;
    asm volatile("{\n\t.reg .pred p;\n\t"
                 "mbarrier.try_wait.parity.acquire.cta.shared::cta.b64 p, [%1], %2;\n\t"
                 "selp.b32 %0, 1, 0, p;\n\t}"
                 : "=r"(done) : "r"(m), "r"(parity) : "memory");
    if (!done) {
        asm volatile("{\n\t.reg .pred P1;\n\t"
                     "WL_%=:\n\t"
                     "mbarrier.try_wait.parity.acquire.cta.shared::cta.b64 P1, [%0], %1, 0x989680;\n\t"
                     "@P1 bra.uni WD_%=;\n\t"
                     "bra.uni WL_%=;\n\t"
                     "WD_%=:\n\t}" :: "r"(m), "r"(parity) : "memory");
    }
}

// ---------------------------------------------------------------------------
// Prep: fold Wf/bf/emb/b1 into E'; fold leaky slopes into W2.
// ---------------------------------------------------------------------------
__global__ void prep_kernel(const float* __restrict__ emb, const float* __restrict__ Wf,
                            const float* __restrict__ bf,  const float* __restrict__ W1,
                            const float* __restrict__ b1,  const float* __restrict__ W2,
                            const float* __restrict__ b2,  const float* __restrict__ Wo,
                            const float* __restrict__ bo) {
    int t = blockIdx.x * blockDim.x + threadIdx.x;
    if (t >= E_SIZE + W_SIZE) return;
    if (t < E_SIZE) {
        int j = t % 12; int r = t / 12; int idx = r % NUM_EX; int h = r / NUM_EX;
        float v = 0.0f;
        if (j < 10) {
            v = b1[h * 10 + j];
            #pragma unroll
            for (int c = 0; c < 3; c++) v += emb[idx * 3 + c] * W1[(h * 8 + c) * 10 + j];
            #pragma unroll
            for (int i = 0; i < 5; i++) v += bf[i] * W1[(h * 8 + 3 + i) * 10 + j];
        }
        g_e[t] = v;
        return;
    }
    int u = t - E_SIZE;
    float v = 0.0f;
    if (u < 1280) {
        int h = u / 64; int o = u % 64;
        if (o < 36) {
            int c = o / 12; int j = o % 12;
            if (j < 10) {
                #pragma unroll
                for (int i = 0; i < 5; i++) v += Wf[c * 5 + i] * W1[(h * 8 + 3 + i) * 10 + j];
            }
        } else if (o < 48) {
            int j = o - 36; if (j < 10) v = 0.505f * W2[h * 10 + j];
        } else if (o < 60) {
            int j = o - 48; if (j < 10) v = 0.495f * W2[h * 10 + j];
        } else if (o == 60) {
            v = b2[h];
        } else if (o == 61) {
            v = Wo[h];
        }
    } else {
        v = bo[0];
    }
    g_w[u] = v;
}

__device__ __forceinline__ float fabs_bits(float x) {
    return __int_as_float(__float_as_int(x) & 0x7FFFFFFF);
}

// ---------------------------------------------------------------------------
// Main: f, e, E' tiles all brought in via cp.async.bulk (no LDG/STS wavefronts),
// uniform weights from __constant__ (uniform port).
// ---------------------------------------------------------------------------
__global__ __launch_bounds__(TPB) void airfit_kernel(const int* __restrict__ e,
                                                     const float* __restrict__ f,
                                                     float* __restrict__ out, int B) {
    extern __shared__ __align__(16) char smem[];
    float4* sF  = reinterpret_cast<float4*>(smem + SM_F);
    int4*   sEv = reinterpret_cast<int4*>(smem + SM_EV);
    float*  sE  = reinterpret_cast<float*>(smem + SM_E);
    const uint32_t mbar = smem_u32(smem + SM_MBAR);

    const int tid = threadIdx.x;
    const bool full = ((size_t)(blockIdx.x + 1)) * TPB <= (size_t)B;

    if (full) {
        if (tid == 0) mbar_init(mbar, 1);
        __syncthreads();
        if (tid == 0) {
            mbar_expect_tx(mbar, F_TILE_B + E_TILE_B + EP_B);
            bulk_g2s(smem_u32(smem + SM_F),  f + (size_t)blockIdx.x * TPB * 60, F_TILE_B, mbar);
            bulk_g2s(smem_u32(smem + SM_EV), e + (size_t)blockIdx.x * TPB * 20, E_TILE_B, mbar);
            bulk_g2s(smem_u32(smem + SM_E),  g_e, EP_B, mbar);
        }
        mbar_wait(mbar, 0);
    } else {
        for (int i = tid; i < E_SIZE; i += TPB) sE[i] = g_e[i];
        __syncthreads();
    }

    int s = blockIdx.x * TPB + tid;
    if (s >= B) return;

    const float4* myF = sF  + tid * 15;   // 240B stride: conflict-free LDS.128
    const int4*   myE = sEv + tid * 5;    // 80B  stride: conflict-free LDS.128
    const float4* fg  = reinterpret_cast<const float4*>(f) + (size_t)s * 15;
    const int4*   eg  = reinterpret_cast<const int4*>(e)   + (size_t)s * 5;

    float res = c_w[1280];

    #pragma unroll
    for (int hg = 0; hg < 5; hg++) {
        float4 fA, fB, fC; int4 ev;
        if (full) {
            fA = myF[hg * 3 + 0]; fB = myF[hg * 3 + 1]; fC = myF[hg * 3 + 2];
            ev = myE[hg];
        } else {
            fA = fg[hg * 3 + 0]; fB = fg[hg * 3 + 1]; fC = fg[hg * 3 + 2];
            ev = eg[hg];
        }
        float g[12] = {fA.x, fA.y, fA.z, fA.w, fB.x, fB.y, fB.z, fB.w,
                       fC.x, fC.y, fC.z, fC.w};
        int idx[4] = {ev.x, ev.y, ev.z, ev.w};

        #pragma unroll
        for (int k = 0; k < 4; k++) {
            const int h = hg * 4 + k;
            const int wb = h * 64;

            const float* Er = &sE[(h * NUM_EX + idx[k]) * 12];
            float4 A0 = *reinterpret_cast<const float4*>(Er);
            float4 A1 = *reinterpret_cast<const float4*>(Er + 4);
            float2 A2 = *reinterpret_cast<const float2*>(Er + 8);
            float a[10] = {A0.x, A0.y, A0.z, A0.w, A1.x, A1.y, A1.z, A1.w, A2.x, A2.y};

            #pragma unroll
            for (int c = 0; c < 3; c++) {
                float fv = g[k * 3 + c];
                #pragma unroll
                for (int j = 0; j < 10; j++)
                    a[j] = fmaf(fv, c_w[wb + c * 12 + j], a[j]);
            }

            // leaky folded: d = b2 + sum a_j*(0.505 w2_j) + |a_j|*(0.495 w2_j)
            float d = c_w[wb + 60];
            #pragma unroll
            for (int j = 0; j < 10; j++) {
                d = fmaf(a[j],            c_w[wb + 36 + j], d);
                d = fmaf(fabs_bits(a[j]), c_w[wb + 48 + j], d);
            }

            // softplus(d) = max(d,0) + log(1+exp(-|d|))
            float m = fmaxf(d, 0.0f);
            float z = __expf(-fabsf(d));
            float spv = m + __logf(1.0f + z);

            res = fmaf(spv, c_w[wb + 61], res);
        }
    }
    out[s] = res;
}

// ---------------------------------------------------------------------------
extern "C" void kernel_launch(void* const* d_in, const int* in_sizes, int n_in,
                              void* d_out, int out_size) {
    const int*   e   = (const int*)  d_in[0];
    const float* f   = (const float*)d_in[1];
    const float* emb = (const float*)d_in[2];
    const float* Wf  = (const float*)d_in[3];
    const float* bf  = (const float*)d_in[4];
    const float* W1  = (const float*)d_in[5];
    const float* b1  = (const float*)d_in[6];
    const float* W2  = (const float*)d_in[7];
    const float* b2  = (const float*)d_in[8];
    const float* Wo  = (const float*)d_in[9];
    const float* bo  = (const float*)d_in[10];
    float* out = (float*)d_out;
    int B = out_size;

    prep_kernel<<<(E_SIZE + W_SIZE + 255) / 256, 256>>>(emb, Wf, bf, W1, b1, W2, b2, Wo, bo);

    void* c_addr = nullptr;
    void* g_addr = nullptr;
    cudaGetSymbolAddress(&c_addr, c_w);
    cudaGetSymbolAddress(&g_addr, g_w);
    cudaMemcpyAsync(c_addr, g_addr, W_SIZE * sizeof(float), cudaMemcpyDeviceToDevice);

    static bool attr_set = false;
    if (!attr_set) {
        cudaFuncSetAttribute(airfit_kernel, cudaFuncAttributeMaxDynamicSharedMemorySize, SM_TOTAL);
        attr_set = true;
    }
    airfit_kernel<<<(B + TPB - 1) / TPB, TPB, SM_TOTAL>>>(e, f, out, B);
}